// round 9
// baseline (speedup 1.0000x reference)
#include <cuda_runtime.h>
#include <math.h>
#include <stdint.h>

// Problem constants (fixed shapes)
#define B_  8
#define N_  4096
#define C_  256
#define K_  4
#define NK_ (N_ * K_)

#define BM 128
#define BN 64
#define BK 16
#define THREADS 256
#define NTILES  (N_ / BN)      // 64 col tiles
#define KSTAGES (C_ / BK)      // 16 k chunks per col tile
#define QTOT    (NTILES * KSTAGES)   // 1024 chunks, continuous pipeline

// smem rows: 16 k-values as (hi,lo) float2 = 128B data, padded to 160B.
// Stride 40 words == 8 banks (mod 32): per-phase conflict-free LDS.64 frags
// (verified round 7).
#define ROW_BYTES   160
#define A_BYTES     (BM * ROW_BYTES)          // 20480
#define B_BYTES     (BN * ROW_BYTES)          // 10240
#define STAGE_BYTES (A_BYTES + B_BYTES)       // 30720
#define STAGES      2
#define SMEM_TOTAL  (STAGES * STAGE_BYTES)    // 61440  (x3 CTAs = 184320)

// tf32 hi/lo split of normalized features (round-4/7 verified layout):
// element k of row r at g_split[r*C + k] = (hi, lo). 64 MB scratch.
__device__ float2 g_split[(size_t)B_ * N_ * C_];

// ---------------------------------------------------------------------------
__device__ __forceinline__ float2 tf32_split(float x) {
    float hi, lo;
    asm("cvt.rna.tf32.f32 %0, %1;" : "=f"(hi) : "f"(x));
    lo = x - hi;
    asm("cvt.rna.tf32.f32 %0, %1;" : "=f"(lo) : "f"(lo));
    return make_float2(hi, lo);
}

// Kernel 1: row-wise L2 normalize + tf32 hi/lo split. One warp per row.
__global__ void normalize_kernel(const float* __restrict__ x) {
    int row  = blockIdx.x * 8 + (threadIdx.x >> 5);
    int lane = threadIdx.x & 31;
    const float4* r = (const float4*)(x + (size_t)row * C_);
    float4 v0 = r[lane];
    float4 v1 = r[lane + 32];
    float s = v0.x * v0.x + v0.y * v0.y + v0.z * v0.z + v0.w * v0.w
            + v1.x * v1.x + v1.y * v1.y + v1.z * v1.z + v1.w * v1.w;
#pragma unroll
    for (int off = 16; off; off >>= 1)
        s += __shfl_xor_sync(0xffffffffu, s, off);
    float nrm = sqrtf(s);
    float2* o = g_split + (size_t)row * C_;
    o[4 * lane + 0]       = tf32_split(v0.x / nrm);
    o[4 * lane + 1]       = tf32_split(v0.y / nrm);
    o[4 * lane + 2]       = tf32_split(v0.z / nrm);
    o[4 * lane + 3]       = tf32_split(v0.w / nrm);
    o[128 + 4 * lane + 0] = tf32_split(v1.x / nrm);
    o[128 + 4 * lane + 1] = tf32_split(v1.y / nrm);
    o[128 + 4 * lane + 2] = tf32_split(v1.z / nrm);
    o[128 + 4 * lane + 3] = tf32_split(v1.w / nrm);
}

// ---------------------------------------------------------------------------
__device__ __forceinline__ void cp16(uint32_t dst, const void* src) {
    asm volatile("cp.async.ca.shared.global [%0], [%1], 16;\n"
                 :: "r"(dst), "l"(src));
}
__device__ __forceinline__ void cp_commit() {
    asm volatile("cp.async.commit_group;\n");
}
__device__ __forceinline__ void mma_tf32(float* c, const uint32_t* a,
                                         uint32_t b0, uint32_t b1) {
    asm volatile(
        "mma.sync.aligned.m16n8k8.row.col.f32.tf32.tf32.f32 "
        "{%0,%1,%2,%3}, {%4,%5,%6,%7}, {%8,%9}, {%0,%1,%2,%3};\n"
        : "+f"(c[0]), "+f"(c[1]), "+f"(c[2]), "+f"(c[3])
        : "r"(a[0]), "r"(a[1]), "r"(a[2]), "r"(a[3]), "r"(b0), "r"(b1));
}

// ---------------------------------------------------------------------------
// Kernel 2: fused 3xTF32 tensor-core sim-GEMM + running top-4 + edge emit.
// CTA: 128 rows x (64 col-tiles of 64). 8 warps, each owns a FULL 16x64 warp
// tile (2 m16 x 8 n8, m16n8k8) -> exactly ONE warp owns each output row.
// CONTINUOUS 2-stage cp.async pipeline across all 1024 chunks: no per-tile
// drain; top-4 fold happens in-flight at each 16-chunk boundary.
// 3 CTAs/SM (occupancy was the round-7 limiter: nothing saturated).
// ---------------------------------------------------------------------------
__global__ __launch_bounds__(THREADS, 3)
void knn_kernel(float* __restrict__ out) {
    extern __shared__ char smem_raw[];
    const int b    = blockIdx.y;
    const int row0 = blockIdx.x * BM;
    const float2* __restrict__ fb = g_split + (size_t)b * N_ * C_;

    const int tid  = threadIdx.x;
    const int warp = tid >> 5;
    const int lane = tid & 31;
    const int gid  = lane >> 2;   // group id 0..7
    const int tq   = lane & 3;    // thread-in-group 0..3
    const int m0   = warp * 16;   // warp's row offset in the CTA tile

    const uint32_t sbase = (uint32_t)__cvta_generic_to_shared(smem_raw);

    // per-thread loader mapping (row = id>>3, chunk = id&7), hoisted
    const int lr = tid >> 3;      // base row (i-th iter adds 32)
    const int lc = tid & 7;       // 16B chunk within the 128B row

    float topv[2][4];
    int   topi[2][4];
#pragma unroll
    for (int i = 0; i < 2; i++)
#pragma unroll
        for (int s = 0; s < 4; s++) { topv[i][s] = -INFINITY; topi[i][s] = 0x7fffffff; }

    float acc[32];
#pragma unroll
    for (int j = 0; j < 32; j++) acc[j] = 0.0f;

    // ---- chunk loader: chunk q -> buffer q&1 ----
#define LOAD_CHUNK(q)                                                           \
    do {                                                                        \
        const int _kk   = ((q) & 15) * BK;                                      \
        const int _col0 = ((q) >> 4) * BN;                                      \
        const uint32_t _sA = sbase + ((q) & 1) * STAGE_BYTES;                   \
        const uint32_t _sB = _sA + A_BYTES;                                     \
        _Pragma("unroll")                                                       \
        for (int i = 0; i < 4; i++) {                                           \
            int r = lr + i * 32;                                                \
            cp16(_sA + r * ROW_BYTES + lc * 16,                                 \
                 fb + (size_t)(row0 + r) * C_ + _kk + lc * 2);                  \
        }                                                                       \
        _Pragma("unroll")                                                       \
        for (int i = 0; i < 2; i++) {                                           \
            int r = lr + i * 32;                                                \
            cp16(_sB + r * ROW_BYTES + lc * 16,                                 \
                 fb + (size_t)(_col0 + r) * C_ + _kk + lc * 2);                 \
        }                                                                       \
        cp_commit();                                                            \
    } while (0)

    LOAD_CHUNK(0);

    for (int q = 0; q < QTOT; q++) {
        asm volatile("cp.async.wait_group 0;\n" ::: "memory");
        __syncthreads();   // chunk q visible to all; all readers of buf q&1
                           // (= compute q-2... q-1 used other buf) are done

        if (q + 1 < QTOT)
            LOAD_CHUNK(q + 1);   // overlaps with compute of chunk q

        // ---- compute chunk q (round-7 verified fragment mapping) ----
        const char* pA = smem_raw + (q & 1) * STAGE_BYTES;
        const char* pB = pA + A_BYTES;
#pragma unroll
        for (int k8 = 0; k8 < BK; k8 += 8) {
            const char* abase = pA + (m0 + gid) * ROW_BYTES;
            float2 l0 = *(const float2*)(abase + (k8 + tq) * 8);
            float2 l1 = *(const float2*)(abase + 8 * ROW_BYTES + (k8 + tq) * 8);
            float2 l2 = *(const float2*)(abase + (k8 + tq + 4) * 8);
            float2 l3 = *(const float2*)(abase + 8 * ROW_BYTES + (k8 + tq + 4) * 8);
            uint32_t ahi[4] = { __float_as_uint(l0.x), __float_as_uint(l1.x),
                                __float_as_uint(l2.x), __float_as_uint(l3.x) };
            uint32_t alo[4] = { __float_as_uint(l0.y), __float_as_uint(l1.y),
                                __float_as_uint(l2.y), __float_as_uint(l3.y) };
#pragma unroll
            for (int nt = 0; nt < 8; nt++) {
                const char* bb = pB + (nt * 8 + gid) * ROW_BYTES;
                float2 p0 = *(const float2*)(bb + (k8 + tq) * 8);
                float2 p1 = *(const float2*)(bb + (k8 + tq + 4) * 8);
                uint32_t bhi0 = __float_as_uint(p0.x), blo0 = __float_as_uint(p0.y);
                uint32_t bhi1 = __float_as_uint(p1.x), blo1 = __float_as_uint(p1.y);
                float* c = acc + nt * 4;
                mma_tf32(c, ahi, bhi0, bhi1);   // hi*hi
                mma_tf32(c, ahi, blo0, blo1);   // hi*lo
                mma_tf32(c, alo, bhi0, bhi1);   // lo*hi
            }
        }

        // ---- col tile done: fold acc into top-4, reset acc (no drain) ----
        if ((q & 15) == 15) {
            const int col0 = (q >> 4) * BN;
#pragma unroll
            for (int i = 0; i < 2; i++) {
                const int g = row0 + m0 + gid + i * 8;
#pragma unroll
                for (int nt = 0; nt < 8; nt++) {
#pragma unroll
                    for (int j = 0; j < 2; j++) {
                        int   col = col0 + nt * 8 + 2 * tq + j;
                        float v   = acc[nt * 4 + i * 2 + j];
                        if (col != g && v > topv[i][3]) {
                            if (v > topv[i][0]) {
                                topv[i][3] = topv[i][2]; topi[i][3] = topi[i][2];
                                topv[i][2] = topv[i][1]; topi[i][2] = topi[i][1];
                                topv[i][1] = topv[i][0]; topi[i][1] = topi[i][0];
                                topv[i][0] = v;          topi[i][0] = col;
                            } else if (v > topv[i][1]) {
                                topv[i][3] = topv[i][2]; topi[i][3] = topi[i][2];
                                topv[i][2] = topv[i][1]; topi[i][2] = topi[i][1];
                                topv[i][1] = v;          topi[i][1] = col;
                            } else if (v > topv[i][2]) {
                                topv[i][3] = topv[i][2]; topi[i][3] = topi[i][2];
                                topv[i][2] = v;          topi[i][2] = col;
                            } else {
                                topv[i][3] = v;          topi[i][3] = col;
                            }
                        }
                    }
                }
            }
#pragma unroll
            for (int j = 0; j < 32; j++) acc[j] = 0.0f;
        }
    }
#undef LOAD_CHUNK

    // ---- merge across the 4 lanes of each quad (quad shares each row),
    //      then emit edges. Output layout (float32):
    //   [b*2*NK .. ]        : src indices
    //   [b*2*NK + NK .. ]   : tgt indices
    //   [B*2*NK + b*NK .. ] : weights
    const size_t ibase = (size_t)b * 2 * NK_;
    const size_t wbase = (size_t)B_ * 2 * NK_ + (size_t)b * NK_;
#pragma unroll
    for (int i = 0; i < 2; i++) {
        const int g = row0 + m0 + gid + i * 8;
        int p = 0;
#pragma unroll
        for (int s = 0; s < 4; s++) {
            float cv = (p < 4) ? topv[i][p] : -INFINITY;
            int   ci = (p < 4) ? topi[i][p] : 0x7fffffff;
#pragma unroll
            for (int off = 1; off <= 2; off <<= 1) {
                float ov = __shfl_xor_sync(0xffffffffu, cv, off);
                int   oi = __shfl_xor_sync(0xffffffffu, ci, off);
                if (ov > cv || (ov == cv && oi < ci)) { cv = ov; ci = oi; }
            }
            if (p < 4 && topi[i][p] == ci) p++;   // winner lane pops its list
            if (tq == s) {
                out[ibase + (size_t)g * K_ + s]       = (float)g;
                out[ibase + NK_ + (size_t)g * K_ + s] = (float)ci;
                out[wbase + (size_t)g * K_ + s]       = cv;
            }
        }
    }
}

// ---------------------------------------------------------------------------
extern "C" void kernel_launch(void* const* d_in, const int* in_sizes, int n_in,
                              void* d_out, int out_size) {
    (void)in_sizes; (void)n_in; (void)out_size;
    const float* x = (const float*)d_in[0];
    float* out = (float*)d_out;

    cudaFuncSetAttribute(knn_kernel,
                         cudaFuncAttributeMaxDynamicSharedMemorySize, SMEM_TOTAL);

    normalize_kernel<<<(B_ * N_) / 8, 256>>>(x);
    dim3 grid(N_ / BM, B_);
    knn_kernel<<<grid, THREADS, SMEM_TOTAL>>>(out);
}

// round 11
// speedup vs baseline: 1.6365x; 1.6365x over previous
#include <cuda_runtime.h>
#include <cuda_bf16.h>
#include <math.h>
#include <stdint.h>

// Problem constants (fixed shapes)
#define B_  8
#define N_  4096
#define C_  256
#define K_  4
#define NK_ (N_ * K_)

#define BM 128
#define BN 64
#define CK 32                    // K per chunk (16 bf16 pairs = 128B row)
#define THREADS 256
#define ZTILES  32               // col tiles per z-half (2048 / 64)
#define CHUNKS  (C_ / CK)        // 8 chunks per col tile
#define QTOT    (ZTILES * CHUNKS)  // 256 chunks per CTA

// smem rows: 16 pairs x 8B = 128B data, padded to 160B (stride 40 words = 8
// banks mod 32 -> conflict-free 8B fragment reads; verified round 7).
#define ROW_BYTES   160
#define A_BYTES     (BM * ROW_BYTES)          // 20480
#define B_BYTES     (BN * ROW_BYTES)          // 10240
#define STAGE_BYTES (A_BYTES + B_BYTES)       // 30720
#define SMEM_TOTAL  (2 * STAGE_BYTES)         // 61440

// Packed bf16 hi/lo split: per row, pair p (= k/2) is 8B:
//   {hi[2p], hi[2p+1], lo[2p], lo[2p+1]}  (uint2: x=hi pair, y=lo pair)
// Row = 128 pairs = 1024B. 32 MB scratch.
__device__ uint2 g_pack[(size_t)B_ * N_ * (C_ / 2)];

// Per-half top-4 partials: [half][b][n][4] = (value, index) pairs. 2 MB.
__device__ float2 g_part[(size_t)2 * B_ * N_ * K_];

// ---------------------------------------------------------------------------
__device__ __forceinline__ uint2 pack_pair(float a, float b) {
    __nv_bfloat16 ha = __float2bfloat16_rn(a);
    __nv_bfloat16 hb = __float2bfloat16_rn(b);
    __nv_bfloat16 la = __float2bfloat16_rn(a - __bfloat162float(ha));
    __nv_bfloat16 lb = __float2bfloat16_rn(b - __bfloat162float(hb));
    uint2 r;
    r.x = (uint32_t)__bfloat16_as_ushort(ha) | ((uint32_t)__bfloat16_as_ushort(hb) << 16);
    r.y = (uint32_t)__bfloat16_as_ushort(la) | ((uint32_t)__bfloat16_as_ushort(lb) << 16);
    return r;
}

// Kernel 1: row-wise L2 normalize + bf16 hi/lo split + pair pack. Warp/row.
__global__ void normalize_kernel(const float* __restrict__ x) {
    int row  = blockIdx.x * 8 + (threadIdx.x >> 5);
    int lane = threadIdx.x & 31;
    const float4* r = (const float4*)(x + (size_t)row * C_);
    float4 v0 = r[lane];
    float4 v1 = r[lane + 32];
    float s = v0.x * v0.x + v0.y * v0.y + v0.z * v0.z + v0.w * v0.w
            + v1.x * v1.x + v1.y * v1.y + v1.z * v1.z + v1.w * v1.w;
#pragma unroll
    for (int off = 16; off; off >>= 1)
        s += __shfl_xor_sync(0xffffffffu, s, off);
    float nrm = sqrtf(s);
    uint2* o = g_pack + (size_t)row * (C_ / 2);
    o[2 * lane + 0]      = pack_pair(v0.x / nrm, v0.y / nrm);
    o[2 * lane + 1]      = pack_pair(v0.z / nrm, v0.w / nrm);
    o[64 + 2 * lane + 0] = pack_pair(v1.x / nrm, v1.y / nrm);
    o[64 + 2 * lane + 1] = pack_pair(v1.z / nrm, v1.w / nrm);
}

// ---------------------------------------------------------------------------
__device__ __forceinline__ void cp16(uint32_t dst, const void* src) {
    asm volatile("cp.async.ca.shared.global [%0], [%1], 16;\n"
                 :: "r"(dst), "l"(src));
}
__device__ __forceinline__ void cp_commit() {
    asm volatile("cp.async.commit_group;\n");
}
__device__ __forceinline__ void mma_bf16(float* c, const uint32_t* a,
                                         uint32_t b0, uint32_t b1) {
    asm volatile(
        "mma.sync.aligned.m16n8k16.row.col.f32.bf16.bf16.f32 "
        "{%0,%1,%2,%3}, {%4,%5,%6,%7}, {%8,%9}, {%0,%1,%2,%3};\n"
        : "+f"(c[0]), "+f"(c[1]), "+f"(c[2]), "+f"(c[3])
        : "r"(a[0]), "r"(a[1]), "r"(a[2]), "r"(a[3]), "r"(b0), "r"(b1));
}

// ---------------------------------------------------------------------------
// Kernel 2: fused 4-product bf16-split tensor-core sim-GEMM + running top-4.
// (hi+lo)*(hi+lo) with ALL four products -> residual is representation-only
// (~5e-7 on sims; the 3-product variant's omitted lo*lo flipped top-k ranks).
// Grid (32, 8, 2): CTA = 128 rows x one z-half (2048 cols, 32 tiles of 64).
// 8 warps, each owns a FULL 16x64 warp tile (m16n8k16) -> one warp per row.
// Continuous 2-stage cp.async pipeline over 256 chunks of K=32.
// Writes per-half top-4 partials to g_part; merge_kernel emits edges.
// ---------------------------------------------------------------------------
__global__ __launch_bounds__(THREADS, 2)
void knn_kernel() {
    extern __shared__ char smem_raw[];
    const int b     = blockIdx.y;
    const int row0  = blockIdx.x * BM;
    const int zhalf = blockIdx.z;
    const int zcol0 = zhalf * (ZTILES * BN);
    const uint2* __restrict__ fb = g_pack + (size_t)b * N_ * (C_ / 2);

    const int tid  = threadIdx.x;
    const int warp = tid >> 5;
    const int lane = tid & 31;
    const int gid  = lane >> 2;   // group id 0..7
    const int tq   = lane & 3;    // thread-in-group 0..3
    const int m0   = warp * 16;   // warp's row offset in the CTA tile

    const uint32_t sbase = (uint32_t)__cvta_generic_to_shared(smem_raw);

    const int lr = tid >> 3;      // loader base row
    const int lc = tid & 7;       // loader 16B chunk within the 128B row

    float topv[2][4];
    int   topi[2][4];
#pragma unroll
    for (int i = 0; i < 2; i++)
#pragma unroll
        for (int s = 0; s < 4; s++) { topv[i][s] = -INFINITY; topi[i][s] = 0x7fffffff; }

    float acc[32];
#pragma unroll
    for (int j = 0; j < 32; j++) acc[j] = 0.0f;

    // ---- chunk loader: chunk q -> buffer q&1. Chunk = 16 pairs (K=32). ----
#define LOAD_CHUNK(q)                                                           \
    do {                                                                        \
        const int _pp   = ((q) & 7) * 16;            /* pair offset in row */   \
        const int _col0 = zcol0 + ((q) >> 3) * BN;                              \
        const uint32_t _sA = sbase + ((q) & 1) * STAGE_BYTES;                   \
        const uint32_t _sB = _sA + A_BYTES;                                     \
        _Pragma("unroll")                                                       \
        for (int i = 0; i < 4; i++) {                                           \
            int r = lr + i * 32;                                                \
            cp16(_sA + r * ROW_BYTES + lc * 16,                                 \
                 fb + (size_t)(row0 + r) * (C_ / 2) + _pp + lc * 2);            \
        }                                                                       \
        _Pragma("unroll")                                                       \
        for (int i = 0; i < 2; i++) {                                           \
            int r = lr + i * 32;                                                \
            cp16(_sB + r * ROW_BYTES + lc * 16,                                 \
                 fb + (size_t)(_col0 + r) * (C_ / 2) + _pp + lc * 2);           \
        }                                                                       \
        cp_commit();                                                            \
    } while (0)

    LOAD_CHUNK(0);

    for (int q = 0; q < QTOT; q++) {
        asm volatile("cp.async.wait_group 0;\n" ::: "memory");
        __syncthreads();

        if (q + 1 < QTOT)
            LOAD_CHUNK(q + 1);   // overlaps with compute of chunk q

        // ---- compute chunk q: 2 k16 blocks (pair blocks {0..7},{8..15}) ----
        const char* pA = smem_raw + (q & 1) * STAGE_BYTES;
        const char* pB = pA + A_BYTES;
#pragma unroll
        for (int kp8 = 0; kp8 < 16; kp8 += 8) {
            const char* abase = pA + (m0 + gid) * ROW_BYTES;
            uint2 l0 = *(const uint2*)(abase + (kp8 + tq) * 8);
            uint2 l1 = *(const uint2*)(abase + 8 * ROW_BYTES + (kp8 + tq) * 8);
            uint2 l2 = *(const uint2*)(abase + (kp8 + tq + 4) * 8);
            uint2 l3 = *(const uint2*)(abase + 8 * ROW_BYTES + (kp8 + tq + 4) * 8);
            uint32_t ahi[4] = { l0.x, l1.x, l2.x, l3.x };
            uint32_t alo[4] = { l0.y, l1.y, l2.y, l3.y };
#pragma unroll
            for (int nt = 0; nt < 8; nt++) {
                const char* bb = pB + (nt * 8 + gid) * ROW_BYTES;
                uint2 p0 = *(const uint2*)(bb + (kp8 + tq) * 8);
                uint2 p1 = *(const uint2*)(bb + (kp8 + tq + 4) * 8);
                float* c = acc + nt * 4;
                mma_bf16(c, ahi, p0.x, p1.x);   // hi*hi
                mma_bf16(c, ahi, p0.y, p1.y);   // hi*lo
                mma_bf16(c, alo, p0.x, p1.x);   // lo*hi
                mma_bf16(c, alo, p0.y, p1.y);   // lo*lo (the round-10 omission)
            }
        }

        // ---- col tile done: fold acc into top-4, reset acc (no drain) ----
        if ((q & 7) == 7) {
            const int col0 = zcol0 + (q >> 3) * BN;
#pragma unroll
            for (int i = 0; i < 2; i++) {
                const int g = row0 + m0 + gid + i * 8;
#pragma unroll
                for (int nt = 0; nt < 8; nt++) {
#pragma unroll
                    for (int j = 0; j < 2; j++) {
                        int   col = col0 + nt * 8 + 2 * tq + j;
                        float v   = acc[nt * 4 + i * 2 + j];
                        if (col != g && v > topv[i][3]) {
                            if (v > topv[i][0]) {
                                topv[i][3] = topv[i][2]; topi[i][3] = topi[i][2];
                                topv[i][2] = topv[i][1]; topi[i][2] = topi[i][1];
                                topv[i][1] = topv[i][0]; topi[i][1] = topi[i][0];
                                topv[i][0] = v;          topi[i][0] = col;
                            } else if (v > topv[i][1]) {
                                topv[i][3] = topv[i][2]; topi[i][3] = topi[i][2];
                                topv[i][2] = topv[i][1]; topi[i][2] = topi[i][1];
                                topv[i][1] = v;          topi[i][1] = col;
                            } else if (v > topv[i][2]) {
                                topv[i][3] = topv[i][2]; topi[i][3] = topi[i][2];
                                topv[i][2] = v;          topi[i][2] = col;
                            } else {
                                topv[i][3] = v;          topi[i][3] = col;
                            }
                        }
                    }
                }
            }
#pragma unroll
            for (int j = 0; j < 32; j++) acc[j] = 0.0f;
        }
    }
#undef LOAD_CHUNK

    // ---- merge across the 4 lanes of each quad, write per-half partials ----
    // g_part layout: ((zhalf*B + b)*N + row)*4 + s = (value, index)
#pragma unroll
    for (int i = 0; i < 2; i++) {
        const int g = row0 + m0 + gid + i * 8;
        float2* dst = g_part + ((size_t)(zhalf * B_ + b) * N_ + g) * K_;
        int p = 0;
#pragma unroll
        for (int s = 0; s < 4; s++) {
            float cv = (p < 4) ? topv[i][p] : -INFINITY;
            int   ci = (p < 4) ? topi[i][p] : 0x7fffffff;
#pragma unroll
            for (int off = 1; off <= 2; off <<= 1) {
                float ov = __shfl_xor_sync(0xffffffffu, cv, off);
                int   oi = __shfl_xor_sync(0xffffffffu, ci, off);
                if (ov > cv || (ov == cv && oi < ci)) { cv = ov; ci = oi; }
            }
            if (p < 4 && topi[i][p] == ci) p++;   // winner lane pops its list
            if (tq == s) dst[s] = make_float2(cv, (float)ci);
        }
    }
}

// ---------------------------------------------------------------------------
// Kernel 3: merge the two column-half top-4 lists per row, emit edges.
// Half-0 indices < half-1 indices, so value-desc / index-asc tie-break is
// preserved by preferring half 0 on equal values.
// Output layout (float32):
//   [b*2*NK .. ]        : src indices
//   [b*2*NK + NK .. ]   : tgt indices
//   [B*2*NK + b*NK .. ] : weights
// ---------------------------------------------------------------------------
__global__ void merge_kernel(float* __restrict__ out) {
    int idx = blockIdx.x * 256 + threadIdx.x;   // 0 .. B*N-1
    int b = idx >> 12, n = idx & (N_ - 1);
    const float2* p0 = g_part + ((size_t)(0 * B_ + b) * N_ + n) * K_;
    const float2* p1 = g_part + ((size_t)(1 * B_ + b) * N_ + n) * K_;
    const size_t ibase = (size_t)b * 2 * NK_;
    const size_t wbase = (size_t)B_ * 2 * NK_ + (size_t)b * NK_;
    int pa = 0, pb = 0;
#pragma unroll
    for (int s = 0; s < 4; s++) {
        float2 a = p0[pa], c = p1[pb];
        bool takeA = (a.x >= c.x);   // ties -> half 0 (lower index)
        float cv = takeA ? a.x : c.x;
        float ci = takeA ? a.y : c.y;
        if (takeA) pa++; else pb++;
        out[ibase + (size_t)n * K_ + s]       = (float)n;
        out[ibase + NK_ + (size_t)n * K_ + s] = ci;
        out[wbase + (size_t)n * K_ + s]       = cv;
    }
}

// ---------------------------------------------------------------------------
extern "C" void kernel_launch(void* const* d_in, const int* in_sizes, int n_in,
                              void* d_out, int out_size) {
    (void)in_sizes; (void)n_in; (void)out_size;
    const float* x = (const float*)d_in[0];
    float* out = (float*)d_out;

    cudaFuncSetAttribute(knn_kernel,
                         cudaFuncAttributeMaxDynamicSharedMemorySize, SMEM_TOTAL);

    normalize_kernel<<<(B_ * N_) / 8, 256>>>(x);
    dim3 grid(N_ / BM, B_, 2);
    knn_kernel<<<grid, THREADS, SMEM_TOTAL>>>();
    merge_kernel<<<(B_ * N_) / 256, 256>>>(out);
}

// round 12
// speedup vs baseline: 1.7821x; 1.0890x over previous
#include <cuda_runtime.h>
#include <cuda_fp16.h>
#include <math.h>
#include <stdint.h>

// Problem constants (fixed shapes)
#define B_  8
#define N_  4096
#define C_  256
#define K_  4
#define NK_ (N_ * K_)

#define BM 128
#define BN 64
#define CK 32                    // K per chunk (16 fp16 pairs = 128B row)
#define THREADS 256
#define ZTILES  32               // col tiles per z-half (2048 / 64)
#define CHUNKS  (C_ / CK)        // 8 chunks per col tile
#define QTOT    (ZTILES * CHUNKS)  // 256 chunks per CTA

// smem rows: 16 pairs x 8B = 128B data, padded to 160B (stride 40 words = 8
// banks mod 32 -> conflict-free 8B fragment reads; verified rounds 7/11).
#define ROW_BYTES   160
#define A_BYTES     (BM * ROW_BYTES)          // 20480
#define B_BYTES     (BN * ROW_BYTES)          // 10240
#define STAGE_BYTES (A_BYTES + B_BYTES)       // 30720
#define SMEM_TOTAL  (2 * STAGE_BYTES)         // 61440

// Packed fp16 hi/lo split: per row, pair p (= k/2) is 8B:
//   {hi[2p], hi[2p+1], lo[2p], lo[2p+1]}  (uint2: x=hi pair, y=lo pair)
// Row = 128 pairs = 1024B. 32 MB scratch.
__device__ uint2 g_pack[(size_t)B_ * N_ * (C_ / 2)];

// Per-half top-4 partials: [half][b][n][4] = (value, index) pairs. 2 MB.
__device__ float2 g_part[(size_t)2 * B_ * N_ * K_];

// ---------------------------------------------------------------------------
__device__ __forceinline__ uint2 pack_pair(float a, float b) {
    __half ha = __float2half_rn(a);
    __half hb = __float2half_rn(b);
    __half la = __float2half_rn(a - __half2float(ha));
    __half lb = __float2half_rn(b - __half2float(hb));
    uint2 r;
    r.x = (uint32_t)__half_as_ushort(ha) | ((uint32_t)__half_as_ushort(hb) << 16);
    r.y = (uint32_t)__half_as_ushort(la) | ((uint32_t)__half_as_ushort(lb) << 16);
    return r;
}

// Kernel 1: row-wise L2 normalize + fp16 hi/lo split + pair pack. Warp/row.
__global__ void normalize_kernel(const float* __restrict__ x) {
    int row  = blockIdx.x * 8 + (threadIdx.x >> 5);
    int lane = threadIdx.x & 31;
    const float4* r = (const float4*)(x + (size_t)row * C_);
    float4 v0 = r[lane];
    float4 v1 = r[lane + 32];
    float s = v0.x * v0.x + v0.y * v0.y + v0.z * v0.z + v0.w * v0.w
            + v1.x * v1.x + v1.y * v1.y + v1.z * v1.z + v1.w * v1.w;
#pragma unroll
    for (int off = 16; off; off >>= 1)
        s += __shfl_xor_sync(0xffffffffu, s, off);
    float nrm = sqrtf(s);
    uint2* o = g_pack + (size_t)row * (C_ / 2);
    o[2 * lane + 0]      = pack_pair(v0.x / nrm, v0.y / nrm);
    o[2 * lane + 1]      = pack_pair(v0.z / nrm, v0.w / nrm);
    o[64 + 2 * lane + 0] = pack_pair(v1.x / nrm, v1.y / nrm);
    o[64 + 2 * lane + 1] = pack_pair(v1.z / nrm, v1.w / nrm);
}

// ---------------------------------------------------------------------------
__device__ __forceinline__ void cp16(uint32_t dst, const void* src) {
    asm volatile("cp.async.ca.shared.global [%0], [%1], 16;\n"
                 :: "r"(dst), "l"(src));
}
__device__ __forceinline__ void cp_commit() {
    asm volatile("cp.async.commit_group;\n");
}
__device__ __forceinline__ void mma_f16(float* c, const uint32_t* a,
                                        uint32_t b0, uint32_t b1) {
    asm volatile(
        "mma.sync.aligned.m16n8k16.row.col.f32.f16.f16.f32 "
        "{%0,%1,%2,%3}, {%4,%5,%6,%7}, {%8,%9}, {%0,%1,%2,%3};\n"
        : "+f"(c[0]), "+f"(c[1]), "+f"(c[2]), "+f"(c[3])
        : "r"(a[0]), "r"(a[1]), "r"(a[2]), "r"(a[3]), "r"(b0), "r"(b1));
}

// ---------------------------------------------------------------------------
// Kernel 2: fused 3-product fp16-split tensor-core sim-GEMM + running top-4.
// fp16 lo captures to 2^-22, so the omitted lo*lo term is <= 2.4e-7 on unit
// vectors (vs 4e-6 for bf16-3x, which flipped ranks). 48 mmas per K=32 chunk
// vs 64 (bf16-4x) / 96 (tf32-3x).
// Grid (32, 8, 2): CTA = 128 rows x one z-half (2048 cols, 32 tiles of 64).
// 8 warps, each owns a FULL 16x64 warp tile (m16n8k16) -> one warp per row.
// Continuous 2-stage cp.async pipeline over 256 chunks of K=32.
// Writes per-half top-4 partials to g_part; merge_kernel emits edges.
// ---------------------------------------------------------------------------
__global__ __launch_bounds__(THREADS, 2)
void knn_kernel() {
    extern __shared__ char smem_raw[];
    const int b     = blockIdx.y;
    const int row0  = blockIdx.x * BM;
    const int zhalf = blockIdx.z;
    const int zcol0 = zhalf * (ZTILES * BN);
    const uint2* __restrict__ fb = g_pack + (size_t)b * N_ * (C_ / 2);

    const int tid  = threadIdx.x;
    const int warp = tid >> 5;
    const int lane = tid & 31;
    const int gid  = lane >> 2;   // group id 0..7
    const int tq   = lane & 3;    // thread-in-group 0..3
    const int m0   = warp * 16;   // warp's row offset in the CTA tile

    const uint32_t sbase = (uint32_t)__cvta_generic_to_shared(smem_raw);

    const int lr = tid >> 3;      // loader base row
    const int lc = tid & 7;       // loader 16B chunk within the 128B row

    float topv[2][4];
    int   topi[2][4];
#pragma unroll
    for (int i = 0; i < 2; i++)
#pragma unroll
        for (int s = 0; s < 4; s++) { topv[i][s] = -INFINITY; topi[i][s] = 0x7fffffff; }

    float acc[32];
#pragma unroll
    for (int j = 0; j < 32; j++) acc[j] = 0.0f;

    // ---- chunk loader: chunk q -> buffer q&1. Chunk = 16 pairs (K=32). ----
#define LOAD_CHUNK(q)                                                           \
    do {                                                                        \
        const int _pp   = ((q) & 7) * 16;            /* pair offset in row */   \
        const int _col0 = zcol0 + ((q) >> 3) * BN;                              \
        const uint32_t _sA = sbase + ((q) & 1) * STAGE_BYTES;                   \
        const uint32_t _sB = _sA + A_BYTES;                                     \
        _Pragma("unroll")                                                       \
        for (int i = 0; i < 4; i++) {                                           \
            int r = lr + i * 32;                                                \
            cp16(_sA + r * ROW_BYTES + lc * 16,                                 \
                 fb + (size_t)(row0 + r) * (C_ / 2) + _pp + lc * 2);            \
        }                                                                       \
        _Pragma("unroll")                                                       \
        for (int i = 0; i < 2; i++) {                                           \
            int r = lr + i * 32;                                                \
            cp16(_sB + r * ROW_BYTES + lc * 16,                                 \
                 fb + (size_t)(_col0 + r) * (C_ / 2) + _pp + lc * 2);           \
        }                                                                       \
        cp_commit();                                                            \
    } while (0)

    LOAD_CHUNK(0);

    for (int q = 0; q < QTOT; q++) {
        asm volatile("cp.async.wait_group 0;\n" ::: "memory");
        __syncthreads();

        if (q + 1 < QTOT)
            LOAD_CHUNK(q + 1);   // overlaps with compute of chunk q

        // ---- compute chunk q: 2 k16 blocks (pair blocks {0..7},{8..15}) ----
        const char* pA = smem_raw + (q & 1) * STAGE_BYTES;
        const char* pB = pA + A_BYTES;
#pragma unroll
        for (int kp8 = 0; kp8 < 16; kp8 += 8) {
            const char* abase = pA + (m0 + gid) * ROW_BYTES;
            uint2 l0 = *(const uint2*)(abase + (kp8 + tq) * 8);
            uint2 l1 = *(const uint2*)(abase + 8 * ROW_BYTES + (kp8 + tq) * 8);
            uint2 l2 = *(const uint2*)(abase + (kp8 + tq + 4) * 8);
            uint2 l3 = *(const uint2*)(abase + 8 * ROW_BYTES + (kp8 + tq + 4) * 8);
            uint32_t ahi[4] = { l0.x, l1.x, l2.x, l3.x };
            uint32_t alo[4] = { l0.y, l1.y, l2.y, l3.y };
#pragma unroll
            for (int nt = 0; nt < 8; nt++) {
                const char* bb = pB + (nt * 8 + gid) * ROW_BYTES;
                uint2 p0 = *(const uint2*)(bb + (kp8 + tq) * 8);
                uint2 p1 = *(const uint2*)(bb + (kp8 + tq + 4) * 8);
                float* c = acc + nt * 4;
                mma_f16(c, ahi, p0.x, p1.x);   // hi*hi
                mma_f16(c, ahi, p0.y, p1.y);   // hi*lo
                mma_f16(c, alo, p0.x, p1.x);   // lo*hi
            }
        }

        // ---- col tile done: fold acc into top-4, reset acc (no drain) ----
        if ((q & 7) == 7) {
            const int col0 = zcol0 + (q >> 3) * BN;
#pragma unroll
            for (int i = 0; i < 2; i++) {
                const int g = row0 + m0 + gid + i * 8;
#pragma unroll
                for (int nt = 0; nt < 8; nt++) {
#pragma unroll
                    for (int j = 0; j < 2; j++) {
                        int   col = col0 + nt * 8 + 2 * tq + j;
                        float v   = acc[nt * 4 + i * 2 + j];
                        if (col != g && v > topv[i][3]) {
                            if (v > topv[i][0]) {
                                topv[i][3] = topv[i][2]; topi[i][3] = topi[i][2];
                                topv[i][2] = topv[i][1]; topi[i][2] = topi[i][1];
                                topv[i][1] = topv[i][0]; topi[i][1] = topi[i][0];
                                topv[i][0] = v;          topi[i][0] = col;
                            } else if (v > topv[i][1]) {
                                topv[i][3] = topv[i][2]; topi[i][3] = topi[i][2];
                                topv[i][2] = topv[i][1]; topi[i][2] = topi[i][1];
                                topv[i][1] = v;          topi[i][1] = col;
                            } else if (v > topv[i][2]) {
                                topv[i][3] = topv[i][2]; topi[i][3] = topi[i][2];
                                topv[i][2] = v;          topi[i][2] = col;
                            } else {
                                topv[i][3] = v;          topi[i][3] = col;
                            }
                        }
                    }
                }
            }
#pragma unroll
            for (int j = 0; j < 32; j++) acc[j] = 0.0f;
        }
    }
#undef LOAD_CHUNK

    // ---- merge across the 4 lanes of each quad, write per-half partials ----
    // g_part layout: ((zhalf*B + b)*N + row)*4 + s = (value, index)
#pragma unroll
    for (int i = 0; i < 2; i++) {
        const int g = row0 + m0 + gid + i * 8;
        float2* dst = g_part + ((size_t)(zhalf * B_ + b) * N_ + g) * K_;
        int p = 0;
#pragma unroll
        for (int s = 0; s < 4; s++) {
            float cv = (p < 4) ? topv[i][p] : -INFINITY;
            int   ci = (p < 4) ? topi[i][p] : 0x7fffffff;
#pragma unroll
            for (int off = 1; off <= 2; off <<= 1) {
                float ov = __shfl_xor_sync(0xffffffffu, cv, off);
                int   oi = __shfl_xor_sync(0xffffffffu, ci, off);
                if (ov > cv || (ov == cv && oi < ci)) { cv = ov; ci = oi; }
            }
            if (p < 4 && topi[i][p] == ci) p++;   // winner lane pops its list
            if (tq == s) dst[s] = make_float2(cv, (float)ci);
        }
    }
}

// ---------------------------------------------------------------------------
// Kernel 3: merge the two column-half top-4 lists per row, emit edges.
// Half-0 indices < half-1 indices, so value-desc / index-asc tie-break is
// preserved by preferring half 0 on equal values.
// Output layout (float32):
//   [b*2*NK .. ]        : src indices
//   [b*2*NK + NK .. ]   : tgt indices
//   [B*2*NK + b*NK .. ] : weights
// ---------------------------------------------------------------------------
__global__ void merge_kernel(float* __restrict__ out) {
    int idx = blockIdx.x * 256 + threadIdx.x;   // 0 .. B*N-1
    int b = idx >> 12, n = idx & (N_ - 1);
    const float2* p0 = g_part + ((size_t)(0 * B_ + b) * N_ + n) * K_;
    const float2* p1 = g_part + ((size_t)(1 * B_ + b) * N_ + n) * K_;
    const size_t ibase = (size_t)b * 2 * NK_;
    const size_t wbase = (size_t)B_ * 2 * NK_ + (size_t)b * NK_;
    int pa = 0, pb = 0;
#pragma unroll
    for (int s = 0; s < 4; s++) {
        float2 a = p0[pa], c = p1[pb];
        bool takeA = (a.x >= c.x);   // ties -> half 0 (lower index)
        float cv = takeA ? a.x : c.x;
        float ci = takeA ? a.y : c.y;
        if (takeA) pa++; else pb++;
        out[ibase + (size_t)n * K_ + s]       = (float)n;
        out[ibase + NK_ + (size_t)n * K_ + s] = ci;
        out[wbase + (size_t)n * K_ + s]       = cv;
    }
}

// ---------------------------------------------------------------------------
extern "C" void kernel_launch(void* const* d_in, const int* in_sizes, int n_in,
                              void* d_out, int out_size) {
    (void)in_sizes; (void)n_in; (void)out_size;
    const float* x = (const float*)d_in[0];
    float* out = (float*)d_out;

    cudaFuncSetAttribute(knn_kernel,
                         cudaFuncAttributeMaxDynamicSharedMemorySize, SMEM_TOTAL);

    normalize_kernel<<<(B_ * N_) / 8, 256>>>(x);
    dim3 grid(N_ / BM, B_, 2);
    knn_kernel<<<grid, THREADS, SMEM_TOTAL>>>();
    merge_kernel<<<(B_ * N_) / 256, 256>>>(out);
}